// round 9
// baseline (speedup 1.0000x reference)
#include <cuda_runtime.h>
#include <cuda_fp16.h>
#include <cstdint>

#define HW     9216
#define IMG_W  96
#define IMG_H  96
#define CCH    192
#define NB     4

// Scratch (no cudaMalloc allowed)
__device__ __half g_x16[(size_t)NB * HW * CCH];          // [b][pix][192] fp16
__device__ __half g_w16[(576 + 192) * CCH];              // w_qkv then w_out, fp16
__device__ float  g_q  [(size_t)NB * HW * CCH];          // [b][48 pg][HW][4] fp32
__device__ __half g_k  [(size_t)NB * HW * CCH];          // [b][24 pg][HW][8] fp16
__device__ __half g_v  [(size_t)NB * HW * CCH];          // [b][24 pg][HW][8] fp16
__device__ __half g_at [(size_t)NB * HW * CCH];          // [b][pix][192] fp16

// ============================================================================
// Weight prep: fp32 -> fp16
// ============================================================================
__global__ void prep_weights(const float* __restrict__ w_qkv,
                             const float* __restrict__ w_out) {
    const int i = blockIdx.x * 256 + threadIdx.x;
    const int total = (576 + 192) * CCH;
    if (i >= total) return;
    const float v = (i < 576 * CCH) ? w_qkv[i] : w_out[i - 576 * CCH];
    g_w16[i] = __float2half_rn(v);
}

// ============================================================================
// Transpose: x[b][192][HW] fp32 -> g_x16[b][pix][192] fp16
// ============================================================================
__global__ void transpose_k(const float* __restrict__ x) {
    __shared__ float tile[32][33];
    const int b  = blockIdx.z;
    const int p0 = blockIdx.x * 32, c0 = blockIdx.y * 32;
    const float* xb = x + (size_t)b * CCH * HW;
    __half* tb = g_x16 + (size_t)b * HW * CCH;
    const int tx = threadIdx.x, ty = threadIdx.y;
    #pragma unroll
    for (int j = 0; j < 32; j += 8)
        tile[ty + j][tx] = xb[(size_t)(c0 + ty + j) * HW + p0 + tx];
    __syncthreads();
    #pragma unroll
    for (int j = 0; j < 32; j += 8)
        tb[(size_t)(p0 + ty + j) * CCH + c0 + tx] = __float2half_rn(tile[tx][ty + j]);
}

// ============================================================================
// fp16 GEMM via mma.sync.m16n8k16: C[m][n] = sum_k A[m][k]*B[n][k]
//   A: [M][192] fp16 per-batch (stride HW*CCH), B: [Ntot][192] fp16.
//   Tile M=128, N=64, K staged 3x64, 8 warps, warp tile 32x32.
//   MODE=1: C fp32 [n][HW] channel-major (d_out).
//   MODE=2: qkv epilogue -> g_q (fp32 d4), g_k/g_v (fp16 d8) via smem staging.
// ============================================================================
#define RS    144                      // smem tile row stride bytes
#define SM_A  0
#define SM_B  (128 * RS)               // 18432
#define SM_GTOT 38912                  // q staging: 128 rows * 304B

__device__ __forceinline__ void mma16816(float* c, const uint32_t* a, const uint32_t* b) {
    asm volatile(
        "mma.sync.aligned.m16n8k16.row.col.f32.f16.f16.f32 "
        "{%0,%1,%2,%3}, {%4,%5,%6,%7}, {%8,%9}, {%0,%1,%2,%3};"
        : "+f"(c[0]), "+f"(c[1]), "+f"(c[2]), "+f"(c[3])
        : "r"(a[0]), "r"(a[1]), "r"(a[2]), "r"(a[3]), "r"(b[0]), "r"(b[1]));
}

template<int MODE>
__global__ __launch_bounds__(256, 2)
void mma_gemm(const __half* __restrict__ A, const __half* __restrict__ B,
              float* __restrict__ Cout)
{
    extern __shared__ char smem[];
    const int t    = threadIdx.x;
    const int wid  = t >> 5, lane = t & 31;
    const int gid  = lane >> 2, tig = lane & 3;
    const int wm   = wid & 3, wn = wid >> 2;
    const int m0   = blockIdx.y * 128;
    const int n0   = blockIdx.x * 64;
    const int b    = blockIdx.z;

    const __half* Ab = A + (size_t)b * HW * CCH + (size_t)m0 * CCH;

    float acc[2][4][4];
    #pragma unroll
    for (int mi = 0; mi < 2; mi++)
        #pragma unroll
        for (int ni = 0; ni < 4; ni++)
            #pragma unroll
            for (int j = 0; j < 4; j++) acc[mi][ni][j] = 0.f;

    #pragma unroll 1
    for (int s = 0; s < 3; s++) {
        const int k0 = s * 64;
        #pragma unroll
        for (int i = 0; i < 4; i++) {       // A: 128x64 fp16 = 1024 16B chunks
            const int idx = t + i * 256;
            const int row = idx >> 3, c8 = (idx & 7) * 8;
            *(uint4*)(smem + SM_A + row * RS + c8 * 2) =
                *(const uint4*)(Ab + (size_t)row * CCH + k0 + c8);
        }
        #pragma unroll
        for (int i = 0; i < 2; i++) {       // B: 64x64 fp16 = 512 chunks
            const int idx = t + i * 256;
            const int row = idx >> 3, c8 = (idx & 7) * 8;
            *(uint4*)(smem + SM_B + row * RS + c8 * 2) =
                *(const uint4*)(B + (size_t)(n0 + row) * CCH + k0 + c8);
        }
        __syncthreads();

        #pragma unroll
        for (int kk = 0; kk < 4; kk++) {
            const uint32_t cb = kk * 32 + tig * 4;
            uint32_t ah[2][4], bh[4][2];
            #pragma unroll
            for (int mi = 0; mi < 2; mi++) {
                const uint32_t r0 = (wm * 32 + mi * 16 + gid) * RS + cb;
                ah[mi][0] = *(const uint32_t*)(smem + SM_A + r0);
                ah[mi][1] = *(const uint32_t*)(smem + SM_A + r0 + 8 * RS);
                ah[mi][2] = *(const uint32_t*)(smem + SM_A + r0 + 16);
                ah[mi][3] = *(const uint32_t*)(smem + SM_A + r0 + 8 * RS + 16);
            }
            #pragma unroll
            for (int ni = 0; ni < 4; ni++) {
                const uint32_t rn = (wn * 32 + ni * 8 + gid) * RS + cb;
                bh[ni][0] = *(const uint32_t*)(smem + SM_B + rn);
                bh[ni][1] = *(const uint32_t*)(smem + SM_B + rn + 16);
            }
            #pragma unroll
            for (int mi = 0; mi < 2; mi++)
                #pragma unroll
                for (int ni = 0; ni < 4; ni++)
                    mma16816(acc[mi][ni], ah[mi], bh[ni]);
        }
        __syncthreads();
    }

    if (MODE == 1) {
        // direct channel-major fp32 stores: Cout[b][col][HW]
        float* Cb = Cout + (size_t)b * CCH * HW;
        #pragma unroll
        for (int mi = 0; mi < 2; mi++) {
            const int row = m0 + wm * 32 + mi * 16 + gid;
            #pragma unroll
            for (int ni = 0; ni < 4; ni++) {
                const int col = n0 + wn * 32 + ni * 8 + 2 * tig;
                Cb[(size_t)col       * HW + row]     = acc[mi][ni][0];
                Cb[(size_t)(col + 1) * HW + row]     = acc[mi][ni][1];
                Cb[(size_t)col       * HW + row + 8] = acc[mi][ni][2];
                Cb[(size_t)(col + 1) * HW + row + 8] = acc[mi][ni][3];
            }
        }
    } else {
        // qkv epilogue via smem staging. n-tile type: 0=q, 1=k, 2=v.
        const int type = n0 / 192;
        if (type == 0) {
            float* st = (float*)smem;           // stride 76 floats (304B)
            #pragma unroll
            for (int mi = 0; mi < 2; mi++) {
                const int rl = wm * 32 + mi * 16 + gid;
                #pragma unroll
                for (int ni = 0; ni < 4; ni++) {
                    const int cl = wn * 32 + ni * 8 + 2 * tig;
                    *(float2*)&st[rl * 76 + cl] =
                        make_float2(acc[mi][ni][0], acc[mi][ni][1]);
                    *(float2*)&st[(rl + 8) * 76 + cl] =
                        make_float2(acc[mi][ni][2], acc[mi][ni][3]);
                }
            }
            __syncthreads();
            #pragma unroll
            for (int i = 0; i < 8; i++) {       // 16 pgs x 128 rows
                const int idx = i * 256 + t;
                const int r = idx & 127, pg = idx >> 7;
                uint4 val = *(uint4*)&st[r * 76 + pg * 4];
                *(uint4*)&g_q[(((size_t)b * 48 + n0 / 4 + pg) * HW + m0 + r) * 4] = val;
            }
        } else {
            __half* st = (__half*)smem;         // stride 72 halves (144B)
            #pragma unroll
            for (int mi = 0; mi < 2; mi++) {
                const int rl = wm * 32 + mi * 16 + gid;
                #pragma unroll
                for (int ni = 0; ni < 4; ni++) {
                    const int cl = wn * 32 + ni * 8 + 2 * tig;
                    *(__half2*)&st[rl * 72 + cl] =
                        __floats2half2_rn(acc[mi][ni][0], acc[mi][ni][1]);
                    *(__half2*)&st[(rl + 8) * 72 + cl] =
                        __floats2half2_rn(acc[mi][ni][2], acc[mi][ni][3]);
                }
            }
            __syncthreads();
            __half* dst = (type == 1) ? g_k : g_v;
            const int pgb = (n0 - type * 192) / 8;
            #pragma unroll
            for (int i = 0; i < 4; i++) {       // 8 pgs x 128 rows
                const int idx = i * 256 + t;
                const int r = idx & 127, pg = idx >> 7;
                uint4 val = *(uint4*)&st[r * 72 + pg * 8];
                *(uint4*)&dst[(((size_t)b * 24 + pgb + pg) * HW + m0 + r) * 8] = val;
            }
        }
    }
}

// ============================================================================
// Neighborhood attention: q fp32 d4-packed, k/v fp16 d8-packed.
// Score dot uses 8 independent partial-sum chains (two float4 accumulators)
// to cut the per-neighbor dependent-FMA critical path from 32 to 4.
// ============================================================================
template<int K, int DIL>
__device__ __forceinline__ void natt_body(const float* __restrict__ sbias,
                                          int head, int b)
{
    const int w   = blockIdx.x * 32 + threadIdx.x;
    const int h   = blockIdx.y * 4  + threadIdx.y;
    const int pix = h * IMG_W + w;

    const float*  qb = g_q + (((size_t)b * 48 + head * 8) * HW + pix) * 4;
    const __half* kb = g_k + ((size_t)b * 24 + head * 4) * HW * 8;
    const __half* vb = g_v + ((size_t)b * 24 + head * 4) * HW * 8;
    const float scale = 0.17677669529663689f;   // 1/sqrt(32)

    float4 q[8];
    #pragma unroll
    for (int i = 0; i < 8; i++) {
        float4 tq = *(const float4*)(qb + (size_t)i * HW * 4);
        q[i] = make_float4(tq.x * scale, tq.y * scale, tq.z * scale, tq.w * scale);
    }

    float4 acc[8];
    #pragma unroll
    for (int i = 0; i < 8; i++) acc[i] = make_float4(0.f, 0.f, 0.f, 0.f);
    float l = 0.f;

    #pragma unroll 1
    for (int di = 0; di < K; di++) {
        const int hh = h + (di - K / 2) * DIL;
        const bool rok = ((unsigned)hh < IMG_H);
        #pragma unroll
        for (int dj = 0; dj < K; dj++) {
            const int ww = w + (dj - K / 2) * DIL;
            const bool ok = rok && ((unsigned)ww < IMG_W);
            const int off = hh * IMG_W + ww;
            float s = 0.f;
            if (ok) {
                const __half* kp = kb + (size_t)off * 8;
                float4 sa = make_float4(0.f, 0.f, 0.f, 0.f);
                float4 sb4 = make_float4(0.f, 0.f, 0.f, 0.f);
                #pragma unroll
                for (int j = 0; j < 4; j++) {
                    uint4 raw = *(const uint4*)(kp + (size_t)j * HW * 8);
                    float2 p0 = __half22float2(*(const __half2*)&raw.x);
                    float2 p1 = __half22float2(*(const __half2*)&raw.y);
                    float2 p2 = __half22float2(*(const __half2*)&raw.z);
                    float2 p3 = __half22float2(*(const __half2*)&raw.w);
                    sa.x += q[2*j].x   * p0.x;  sa.y += q[2*j].y   * p0.y;
                    sa.z += q[2*j].z   * p1.x;  sa.w += q[2*j].w   * p1.y;
                    sb4.x += q[2*j+1].x * p2.x; sb4.y += q[2*j+1].y * p2.y;
                    sb4.z += q[2*j+1].z * p3.x; sb4.w += q[2*j+1].w * p3.y;
                }
                const float t0 = sa.x + sa.y,  t1 = sa.z + sa.w;
                const float t2 = sb4.x + sb4.y, t3 = sb4.z + sb4.w;
                s = (t0 + t1) + (t2 + t3);
            }
            const float e = __expf(s + sbias[di * K + dj]);
            l += e;
            if (ok) {
                const __half* vp = vb + (size_t)off * 8;
                #pragma unroll
                for (int j = 0; j < 4; j++) {
                    uint4 raw = *(const uint4*)(vp + (size_t)j * HW * 8);
                    float2 p0 = __half22float2(*(const __half2*)&raw.x);
                    float2 p1 = __half22float2(*(const __half2*)&raw.y);
                    float2 p2 = __half22float2(*(const __half2*)&raw.z);
                    float2 p3 = __half22float2(*(const __half2*)&raw.w);
                    acc[2*j].x   += e * p0.x; acc[2*j].y   += e * p0.y;
                    acc[2*j].z   += e * p1.x; acc[2*j].w   += e * p1.y;
                    acc[2*j+1].x += e * p2.x; acc[2*j+1].y += e * p2.y;
                    acc[2*j+1].z += e * p3.x; acc[2*j+1].w += e * p3.y;
                }
            }
        }
    }

    const float il = 1.f / l;
    const size_t ob = ((size_t)b * HW + pix) * CCH + head * 32;
    #pragma unroll
    for (int j = 0; j < 4; j++) {
        __half2 h0 = __floats2half2_rn(acc[2*j].x   * il, acc[2*j].y   * il);
        __half2 h1 = __floats2half2_rn(acc[2*j].z   * il, acc[2*j].w   * il);
        __half2 h2 = __floats2half2_rn(acc[2*j+1].x * il, acc[2*j+1].y * il);
        __half2 h3 = __floats2half2_rn(acc[2*j+1].z * il, acc[2*j+1].w * il);
        uint4 val;
        val.x = *(uint32_t*)&h0; val.y = *(uint32_t*)&h1;
        val.z = *(uint32_t*)&h2; val.w = *(uint32_t*)&h3;
        *(uint4*)&g_at[ob + j * 8] = val;
    }
}

__global__ __launch_bounds__(128, 6)
void natt_all(const float* __restrict__ b0, const float* __restrict__ b1,
              const float* __restrict__ b2, const float* __restrict__ b3,
              const float* __restrict__ b4, const float* __restrict__ b5)
{
    __shared__ float sb[81];
    const int z = blockIdx.z;
    const int head = z % 6;
    const int b    = z / 6;
    const float* bp;
    int k2;
    switch (head) {
        case 0: bp = b0; k2 = 9;  break;
        case 1: bp = b1; k2 = 25; break;
        case 2: bp = b2; k2 = 49; break;
        case 3: bp = b3; k2 = 49; break;
        case 4: bp = b4; k2 = 81; break;
        default: bp = b5; k2 = 81; break;
    }
    const int t = threadIdx.y * 32 + threadIdx.x;
    if (t < k2) sb[t] = bp[t];
    __syncthreads();
    switch (head) {
        case 0: natt_body<3, 1>(sb, 0, b); break;
        case 1: natt_body<5, 2>(sb, 1, b); break;
        case 2: natt_body<7, 1>(sb, 2, b); break;
        case 3: natt_body<7, 3>(sb, 3, b); break;
        case 4: natt_body<9, 1>(sb, 4, b); break;
        case 5: natt_body<9, 2>(sb, 5, b); break;
    }
}

// ============================================================================
extern "C" void kernel_launch(void* const* d_in, const int* in_sizes, int n_in,
                              void* d_out, int out_size)
{
    (void)in_sizes; (void)n_in; (void)out_size;
    const float* x     = (const float*)d_in[0];
    const float* w_qkv = (const float*)d_in[1];
    const float* w_out = (const float*)d_in[2];
    const float* b0 = (const float*)d_in[3];
    const float* b1 = (const float*)d_in[4];
    const float* b2 = (const float*)d_in[5];
    const float* b3 = (const float*)d_in[6];
    const float* b4 = (const float*)d_in[7];
    const float* b5 = (const float*)d_in[8];

    __half *x16, *w16, *at16;
    cudaGetSymbolAddress((void**)&x16,  g_x16);
    cudaGetSymbolAddress((void**)&w16,  g_w16);
    cudaGetSymbolAddress((void**)&at16, g_at);

    cudaFuncSetAttribute(mma_gemm<1>, cudaFuncAttributeMaxDynamicSharedMemorySize, SM_GTOT);
    cudaFuncSetAttribute(mma_gemm<2>, cudaFuncAttributeMaxDynamicSharedMemorySize, SM_GTOT);

    prep_weights<<<(768 * CCH + 255) / 256, 256>>>(w_qkv, w_out);
    transpose_k<<<dim3(HW / 32, CCH / 32, NB), dim3(32, 8)>>>(x);

    // qkv = x16 @ w_qkv^T  -> g_q / g_k / g_v (packed layouts)
    mma_gemm<2><<<dim3(576 / 64, HW / 128, NB), 256, SM_GTOT>>>(x16, w16, nullptr);

    natt_all<<<dim3(IMG_W / 32, IMG_H / 4, NB * 6), dim3(32, 4)>>>(
        b0, b1, b2, b3, b4, b5);

    // d_out[b][ch][pix] = (attn @ w_out^T)^T
    mma_gemm<1><<<dim3(CCH / 64, HW / 128, NB), 256, SM_GTOT>>>(
        at16, w16 + 576 * CCH, (float*)d_out);
}

// round 10
// speedup vs baseline: 1.4001x; 1.4001x over previous
#include <cuda_runtime.h>
#include <cuda_fp16.h>
#include <cstdint>

#define HW     9216
#define IMG_W  96
#define IMG_H  96
#define CCH    192
#define NB     4

// Scratch (no cudaMalloc allowed)
__device__ __half g_x16[(size_t)NB * HW * CCH];          // [b][pix][192] fp16
__device__ __half g_w16[(576 + 192) * CCH];              // w_qkv then w_out, fp16
__device__ __half g_q  [(size_t)NB * HW * CCH];          // [b][24 pg][HW][8] fp16 (pre-scaled)
__device__ __half g_k  [(size_t)NB * HW * CCH];          // [b][24 pg][HW][8] fp16
__device__ __half g_v  [(size_t)NB * HW * CCH];          // [b][24 pg][HW][8] fp16
__device__ __half g_at [(size_t)NB * HW * CCH];          // [b][pix][192] fp16

// ============================================================================
// Weight prep: fp32 -> fp16
// ============================================================================
__global__ void prep_weights(const float* __restrict__ w_qkv,
                             const float* __restrict__ w_out) {
    const int i = blockIdx.x * 256 + threadIdx.x;
    const int total = (576 + 192) * CCH;
    if (i >= total) return;
    const float v = (i < 576 * CCH) ? w_qkv[i] : w_out[i - 576 * CCH];
    g_w16[i] = __float2half_rn(v);
}

// ============================================================================
// Transpose: x[b][192][HW] fp32 -> g_x16[b][pix][192] fp16
// ============================================================================
__global__ void transpose_k(const float* __restrict__ x) {
    __shared__ float tile[32][33];
    const int b  = blockIdx.z;
    const int p0 = blockIdx.x * 32, c0 = blockIdx.y * 32;
    const float* xb = x + (size_t)b * CCH * HW;
    __half* tb = g_x16 + (size_t)b * HW * CCH;
    const int tx = threadIdx.x, ty = threadIdx.y;
    #pragma unroll
    for (int j = 0; j < 32; j += 8)
        tile[ty + j][tx] = xb[(size_t)(c0 + ty + j) * HW + p0 + tx];
    __syncthreads();
    #pragma unroll
    for (int j = 0; j < 32; j += 8)
        tb[(size_t)(p0 + ty + j) * CCH + c0 + tx] = __float2half_rn(tile[tx][ty + j]);
}

// ============================================================================
// fp16 GEMM via mma.sync.m16n8k16: C[m][n] = sum_k A[m][k]*B[n][k]
//   Tile M=128, N=64, K staged 3x64, 8 warps, warp tile 32x32.
//   MODE=1: C fp32 [n][HW] channel-major (d_out).
//   MODE=2: qkv epilogue -> g_q/g_k/g_v fp16 d8-packed (q pre-scaled by 1/sqrt(32)).
// ============================================================================
#define RS    144                      // smem tile row stride bytes
#define SM_A  0
#define SM_B  (128 * RS)               // 18432
#define SM_GTOT (SM_B + 64 * RS)       // 27648 (>= 128*144 staging)

__device__ __forceinline__ void mma16816(float* c, const uint32_t* a, const uint32_t* b) {
    asm volatile(
        "mma.sync.aligned.m16n8k16.row.col.f32.f16.f16.f32 "
        "{%0,%1,%2,%3}, {%4,%5,%6,%7}, {%8,%9}, {%0,%1,%2,%3};"
        : "+f"(c[0]), "+f"(c[1]), "+f"(c[2]), "+f"(c[3])
        : "r"(a[0]), "r"(a[1]), "r"(a[2]), "r"(a[3]), "r"(b[0]), "r"(b[1]));
}

template<int MODE>
__global__ __launch_bounds__(256, 2)
void mma_gemm(const __half* __restrict__ A, const __half* __restrict__ B,
              float* __restrict__ Cout)
{
    extern __shared__ char smem[];
    const int t    = threadIdx.x;
    const int wid  = t >> 5, lane = t & 31;
    const int gid  = lane >> 2, tig = lane & 3;
    const int wm   = wid & 3, wn = wid >> 2;
    const int m0   = blockIdx.y * 128;
    const int n0   = blockIdx.x * 64;
    const int b    = blockIdx.z;

    const __half* Ab = A + (size_t)b * HW * CCH + (size_t)m0 * CCH;

    float acc[2][4][4];
    #pragma unroll
    for (int mi = 0; mi < 2; mi++)
        #pragma unroll
        for (int ni = 0; ni < 4; ni++)
            #pragma unroll
            for (int j = 0; j < 4; j++) acc[mi][ni][j] = 0.f;

    #pragma unroll 1
    for (int s = 0; s < 3; s++) {
        const int k0 = s * 64;
        #pragma unroll
        for (int i = 0; i < 4; i++) {       // A: 128x64 fp16 = 1024 16B chunks
            const int idx = t + i * 256;
            const int row = idx >> 3, c8 = (idx & 7) * 8;
            *(uint4*)(smem + SM_A + row * RS + c8 * 2) =
                *(const uint4*)(Ab + (size_t)row * CCH + k0 + c8);
        }
        #pragma unroll
        for (int i = 0; i < 2; i++) {       // B: 64x64 fp16 = 512 chunks
            const int idx = t + i * 256;
            const int row = idx >> 3, c8 = (idx & 7) * 8;
            *(uint4*)(smem + SM_B + row * RS + c8 * 2) =
                *(const uint4*)(B + (size_t)(n0 + row) * CCH + k0 + c8);
        }
        __syncthreads();

        #pragma unroll
        for (int kk = 0; kk < 4; kk++) {
            const uint32_t cb = kk * 32 + tig * 4;
            uint32_t ah[2][4], bh[4][2];
            #pragma unroll
            for (int mi = 0; mi < 2; mi++) {
                const uint32_t r0 = (wm * 32 + mi * 16 + gid) * RS + cb;
                ah[mi][0] = *(const uint32_t*)(smem + SM_A + r0);
                ah[mi][1] = *(const uint32_t*)(smem + SM_A + r0 + 8 * RS);
                ah[mi][2] = *(const uint32_t*)(smem + SM_A + r0 + 16);
                ah[mi][3] = *(const uint32_t*)(smem + SM_A + r0 + 8 * RS + 16);
            }
            #pragma unroll
            for (int ni = 0; ni < 4; ni++) {
                const uint32_t rn = (wn * 32 + ni * 8 + gid) * RS + cb;
                bh[ni][0] = *(const uint32_t*)(smem + SM_B + rn);
                bh[ni][1] = *(const uint32_t*)(smem + SM_B + rn + 16);
            }
            #pragma unroll
            for (int mi = 0; mi < 2; mi++)
                #pragma unroll
                for (int ni = 0; ni < 4; ni++)
                    mma16816(acc[mi][ni], ah[mi], bh[ni]);
        }
        __syncthreads();
    }

    if (MODE == 1) {
        // direct channel-major fp32 stores: Cout[b][col][HW]
        float* Cb = Cout + (size_t)b * CCH * HW;
        #pragma unroll
        for (int mi = 0; mi < 2; mi++) {
            const int row = m0 + wm * 32 + mi * 16 + gid;
            #pragma unroll
            for (int ni = 0; ni < 4; ni++) {
                const int col = n0 + wn * 32 + ni * 8 + 2 * tig;
                Cb[(size_t)col       * HW + row]     = acc[mi][ni][0];
                Cb[(size_t)(col + 1) * HW + row]     = acc[mi][ni][1];
                Cb[(size_t)col       * HW + row + 8] = acc[mi][ni][2];
                Cb[(size_t)(col + 1) * HW + row + 8] = acc[mi][ni][3];
            }
        }
    } else {
        // unified qkv epilogue: fp16 d8-packed via smem staging.
        const int type = n0 / 192;             // 0=q, 1=k, 2=v
        const float sc = (type == 0) ? 0.17677669529663689f : 1.0f;
        __half* st = (__half*)smem;            // stride 72 halves (144B)
        #pragma unroll
        for (int mi = 0; mi < 2; mi++) {
            const int rl = wm * 32 + mi * 16 + gid;
            #pragma unroll
            for (int ni = 0; ni < 4; ni++) {
                const int cl = wn * 32 + ni * 8 + 2 * tig;
                *(__half2*)&st[rl * 72 + cl] =
                    __floats2half2_rn(acc[mi][ni][0] * sc, acc[mi][ni][1] * sc);
                *(__half2*)&st[(rl + 8) * 72 + cl] =
                    __floats2half2_rn(acc[mi][ni][2] * sc, acc[mi][ni][3] * sc);
            }
        }
        __syncthreads();
        __half* dst = (type == 0) ? g_q : (type == 1) ? g_k : g_v;
        const int pgb = (n0 - type * 192) / 8;
        #pragma unroll
        for (int i = 0; i < 4; i++) {          // 8 pgs x 128 rows
            const int idx = i * 256 + t;
            const int r = idx & 127, pg = idx >> 7;
            uint4 val = *(uint4*)&st[r * 72 + pg * 8];
            *(uint4*)&dst[(((size_t)b * 24 + pgb + pg) * HW + m0 + r) * 8] = val;
        }
    }
}

// ============================================================================
// Neighborhood attention: q/k/v all fp16 d8-packed; q pre-scaled.
// Score via HFMA2 (2 half2 accumulators); value accumulate stays fp32.
// ============================================================================
template<int K, int DIL>
__device__ __forceinline__ void natt_body(const float* __restrict__ sbias,
                                          int head, int b)
{
    const int w   = blockIdx.x * 32 + threadIdx.x;
    const int h   = blockIdx.y * 4  + threadIdx.y;
    const int pix = h * IMG_W + w;

    const __half* qp = g_q + (((size_t)b * 24 + head * 4) * HW + pix) * 8;
    const __half* kb = g_k + ((size_t)b * 24 + head * 4) * HW * 8;
    const __half* vb = g_v + ((size_t)b * 24 + head * 4) * HW * 8;

    __half2 qh[16];
    #pragma unroll
    for (int j = 0; j < 4; j++) {
        uint4 r = *(const uint4*)(qp + (size_t)j * HW * 8);
        qh[4 * j + 0] = *(const __half2*)&r.x;
        qh[4 * j + 1] = *(const __half2*)&r.y;
        qh[4 * j + 2] = *(const __half2*)&r.z;
        qh[4 * j + 3] = *(const __half2*)&r.w;
    }

    float4 acc[8];
    #pragma unroll
    for (int i = 0; i < 8; i++) acc[i] = make_float4(0.f, 0.f, 0.f, 0.f);
    float l = 0.f;

    #pragma unroll 1
    for (int di = 0; di < K; di++) {
        const int hh = h + (di - K / 2) * DIL;
        const bool rok = ((unsigned)hh < IMG_H);
        #pragma unroll
        for (int dj = 0; dj < K; dj++) {
            const int ww = w + (dj - K / 2) * DIL;
            const bool ok = rok && ((unsigned)ww < IMG_W);
            const int off = hh * IMG_W + ww;
            float s = 0.f;
            if (ok) {
                const __half* kp = kb + (size_t)off * 8;
                __half2 s0 = __float2half2_rn(0.f);
                __half2 s1 = __float2half2_rn(0.f);
                #pragma unroll
                for (int j = 0; j < 4; j++) {
                    uint4 raw = *(const uint4*)(kp + (size_t)j * HW * 8);
                    s0 = __hfma2(qh[4 * j + 0], *(const __half2*)&raw.x, s0);
                    s1 = __hfma2(qh[4 * j + 1], *(const __half2*)&raw.y, s1);
                    s0 = __hfma2(qh[4 * j + 2], *(const __half2*)&raw.z, s0);
                    s1 = __hfma2(qh[4 * j + 3], *(const __half2*)&raw.w, s1);
                }
                const float2 sf = __half22float2(__hadd2(s0, s1));
                s = sf.x + sf.y;
            }
            const float e = __expf(s + sbias[di * K + dj]);
            l += e;
            if (ok) {
                const __half* vp = vb + (size_t)off * 8;
                #pragma unroll
                for (int j = 0; j < 4; j++) {
                    uint4 raw = *(const uint4*)(vp + (size_t)j * HW * 8);
                    float2 p0 = __half22float2(*(const __half2*)&raw.x);
                    float2 p1 = __half22float2(*(const __half2*)&raw.y);
                    float2 p2 = __half22float2(*(const __half2*)&raw.z);
                    float2 p3 = __half22float2(*(const __half2*)&raw.w);
                    acc[2*j].x   += e * p0.x; acc[2*j].y   += e * p0.y;
                    acc[2*j].z   += e * p1.x; acc[2*j].w   += e * p1.y;
                    acc[2*j+1].x += e * p2.x; acc[2*j+1].y += e * p2.y;
                    acc[2*j+1].z += e * p3.x; acc[2*j+1].w += e * p3.y;
                }
            }
        }
    }

    const float il = 1.f / l;
    const size_t ob = ((size_t)b * HW + pix) * CCH + head * 32;
    #pragma unroll
    for (int j = 0; j < 4; j++) {
        __half2 h0 = __floats2half2_rn(acc[2*j].x   * il, acc[2*j].y   * il);
        __half2 h1 = __floats2half2_rn(acc[2*j].z   * il, acc[2*j].w   * il);
        __half2 h2 = __floats2half2_rn(acc[2*j+1].x * il, acc[2*j+1].y * il);
        __half2 h3 = __floats2half2_rn(acc[2*j+1].z * il, acc[2*j+1].w * il);
        uint4 val;
        val.x = *(uint32_t*)&h0; val.y = *(uint32_t*)&h1;
        val.z = *(uint32_t*)&h2; val.w = *(uint32_t*)&h3;
        *(uint4*)&g_at[ob + j * 8] = val;
    }
}

__global__ __launch_bounds__(128, 7)
void natt_all(const float* __restrict__ b0, const float* __restrict__ b1,
              const float* __restrict__ b2, const float* __restrict__ b3,
              const float* __restrict__ b4, const float* __restrict__ b5)
{
    __shared__ float sb[81];
    // Heavy heads first: tail of the grid is cheap CTAs.
    const int HORD[6] = {4, 5, 3, 2, 1, 0};
    const int z = blockIdx.z;
    const int head = HORD[z >> 2];
    const int b    = z & 3;
    const float* bp;
    int k2;
    switch (head) {
        case 0: bp = b0; k2 = 9;  break;
        case 1: bp = b1; k2 = 25; break;
        case 2: bp = b2; k2 = 49; break;
        case 3: bp = b3; k2 = 49; break;
        case 4: bp = b4; k2 = 81; break;
        default: bp = b5; k2 = 81; break;
    }
    const int t = threadIdx.y * 32 + threadIdx.x;
    if (t < k2) sb[t] = bp[t];
    __syncthreads();
    switch (head) {
        case 0: natt_body<3, 1>(sb, 0, b); break;
        case 1: natt_body<5, 2>(sb, 1, b); break;
        case 2: natt_body<7, 1>(sb, 2, b); break;
        case 3: natt_body<7, 3>(sb, 3, b); break;
        case 4: natt_body<9, 1>(sb, 4, b); break;
        case 5: natt_body<9, 2>(sb, 5, b); break;
    }
}

// ============================================================================
extern "C" void kernel_launch(void* const* d_in, const int* in_sizes, int n_in,
                              void* d_out, int out_size)
{
    (void)in_sizes; (void)n_in; (void)out_size;
    const float* x     = (const float*)d_in[0];
    const float* w_qkv = (const float*)d_in[1];
    const float* w_out = (const float*)d_in[2];
    const float* b0 = (const float*)d_in[3];
    const float* b1 = (const float*)d_in[4];
    const float* b2 = (const float*)d_in[5];
    const float* b3 = (const float*)d_in[6];
    const float* b4 = (const float*)d_in[7];
    const float* b5 = (const float*)d_in[8];

    __half *x16, *w16, *at16;
    cudaGetSymbolAddress((void**)&x16,  g_x16);
    cudaGetSymbolAddress((void**)&w16,  g_w16);
    cudaGetSymbolAddress((void**)&at16, g_at);

    cudaFuncSetAttribute(mma_gemm<1>, cudaFuncAttributeMaxDynamicSharedMemorySize, SM_GTOT);
    cudaFuncSetAttribute(mma_gemm<2>, cudaFuncAttributeMaxDynamicSharedMemorySize, SM_GTOT);

    prep_weights<<<(768 * CCH + 255) / 256, 256>>>(w_qkv, w_out);
    transpose_k<<<dim3(HW / 32, CCH / 32, NB), dim3(32, 8)>>>(x);

    // qkv = x16 @ w_qkv^T  -> g_q / g_k / g_v (fp16 d8-packed, q pre-scaled)
    mma_gemm<2><<<dim3(576 / 64, HW / 128, NB), 256, SM_GTOT>>>(x16, w16, nullptr);

    natt_all<<<dim3(IMG_W / 32, IMG_H / 4, NB * 6), dim3(32, 4)>>>(
        b0, b1, b2, b3, b4, b5);

    // d_out[b][ch][pix] = (attn @ w_out^T)^T
    mma_gemm<1><<<dim3(CCH / 64, HW / 128, NB), 256, SM_GTOT>>>(
        at16, w16 + 576 * CCH, (float*)d_out);
}